// round 1
// baseline (speedup 1.0000x reference)
#include <cuda_runtime.h>
#include <cstdint>

// Problem dims
#define TT 1024
#define BB 8
#define DD 1024
#define HH 16
#define DH 64
#define ROWS (TT*BB)            // 8192
#define SEGC 8388608            // ROWS*DD elements per projection

// Scratch: 5 projections (q,k,v,apre,bpre) + alpha/beta
__device__ float g_proj[5u * 8388608u];   // ~168 MB
__device__ float g_alpha[ROWS * HH];
__device__ float g_beta[ROWS * HH];

// ---------------- packed f32x2 helpers (sm_103a FFMA2) ----------------
__device__ __forceinline__ unsigned long long pk2(float x, float y) {
    unsigned long long r;
    asm("mov.b64 %0, {%1, %2};" : "=l"(r) : "f"(x), "f"(y));
    return r;
}
__device__ __forceinline__ void ffma2(unsigned long long& d,
                                      unsigned long long a,
                                      unsigned long long b) {
    asm("fma.rn.f32x2 %0, %1, %2, %0;" : "+l"(d) : "l"(a), "l"(b));
}
__device__ __forceinline__ float lo32(unsigned long long u) {
    return __uint_as_float((unsigned)u);
}
__device__ __forceinline__ float hi32(unsigned long long u) {
    return __uint_as_float((unsigned)(u >> 32));
}

// ---------------- cp.async helpers ----------------
__device__ __forceinline__ void cpa16(void* dst, const void* src) {
    unsigned u = (unsigned)__cvta_generic_to_shared(dst);
    asm volatile("cp.async.cg.shared.global [%0], [%1], 16;" :: "r"(u), "l"(src));
}
__device__ __forceinline__ void cpa4(void* dst, const void* src) {
    unsigned u = (unsigned)__cvta_generic_to_shared(dst);
    asm volatile("cp.async.ca.shared.global [%0], [%1], 4;" :: "r"(u), "l"(src));
}
#define CP_COMMIT() asm volatile("cp.async.commit_group;")
#define CP_WAIT2()  asm volatile("cp.async.wait_group 2;")

// =====================================================================
// Kernel 1: fused 5-way GEMM  Y[seg] = X @ W[seg]^T
// X: (8192,1024) row-major; W: (1024,1024) row-major (both K-contiguous)
// Tiles: BM=128, BN=128, BK=16, 256 threads, 8x8 per thread, FFMA2 packed.
// grid = (64, 40): y>>3 = segment, y&7 = N tile
// =====================================================================
__global__ __launch_bounds__(256, 2)
void gemm5(const float* __restrict__ X,
           const float* __restrict__ W0, const float* __restrict__ W1,
           const float* __restrict__ W2, const float* __restrict__ W3,
           const float* __restrict__ W4)
{
    __shared__ __align__(16) float As[2][16][132];
    __shared__ __align__(16) float Bs[2][16][132];

    const int seg = blockIdx.y >> 3;
    const float* W = (seg == 0) ? W0 : (seg == 1) ? W1 : (seg == 2) ? W2
                     : (seg == 3) ? W3 : W4;
    const int mBase = blockIdx.x * 128;
    const int nBase = (blockIdx.y & 7) * 128;
    const int tid = threadIdx.x;
    const int tx = tid & 15, ty = tid >> 4;
    const int m0 = ty * 8, n0 = tx * 8;

    // global-load mapping: 2 float4 per operand per K-tile
    const int r0 = tid >> 2;         // 0..63
    const int c0 = tid & 3;          // float4 column within 16-wide K tile
    const int r1 = r0 + 64;
    const float* Ag = X + (size_t)mBase * DD;
    const float* Bg = W + (size_t)nBase * DD;

    unsigned long long acc[8][4];
#pragma unroll
    for (int i = 0; i < 8; i++)
#pragma unroll
        for (int j = 0; j < 4; j++) acc[i][j] = 0ull;

    // preload K-tile 0
    float4 a0 = *(const float4*)(Ag + (size_t)r0 * DD + c0 * 4);
    float4 a1 = *(const float4*)(Ag + (size_t)r1 * DD + c0 * 4);
    float4 b0 = *(const float4*)(Bg + (size_t)r0 * DD + c0 * 4);
    float4 b1 = *(const float4*)(Bg + (size_t)r1 * DD + c0 * 4);
    {
        const int kc = c0 * 4;
        As[0][kc+0][r0] = a0.x; As[0][kc+1][r0] = a0.y; As[0][kc+2][r0] = a0.z; As[0][kc+3][r0] = a0.w;
        As[0][kc+0][r1] = a1.x; As[0][kc+1][r1] = a1.y; As[0][kc+2][r1] = a1.z; As[0][kc+3][r1] = a1.w;
        Bs[0][kc+0][r0] = b0.x; Bs[0][kc+1][r0] = b0.y; Bs[0][kc+2][r0] = b0.z; Bs[0][kc+3][r0] = b0.w;
        Bs[0][kc+0][r1] = b1.x; Bs[0][kc+1][r1] = b1.y; Bs[0][kc+2][r1] = b1.z; Bs[0][kc+3][r1] = b1.w;
    }
    __syncthreads();

    for (int kt = 0; kt < 64; kt++) {
        const int cur = kt & 1;
        if (kt < 63) {
            const int kOff = (kt + 1) * 16 + c0 * 4;
            a0 = *(const float4*)(Ag + (size_t)r0 * DD + kOff);
            a1 = *(const float4*)(Ag + (size_t)r1 * DD + kOff);
            b0 = *(const float4*)(Bg + (size_t)r0 * DD + kOff);
            b1 = *(const float4*)(Bg + (size_t)r1 * DD + kOff);
        }
#pragma unroll
        for (int kk = 0; kk < 16; kk++) {
            float4 Af0 = *(const float4*)&As[cur][kk][m0];
            float4 Af1 = *(const float4*)&As[cur][kk][m0 + 4];
            float4 Bf0 = *(const float4*)&Bs[cur][kk][n0];
            float4 Bf1 = *(const float4*)&Bs[cur][kk][n0 + 4];
            unsigned long long bp0 = pk2(Bf0.x, Bf0.y);
            unsigned long long bp1 = pk2(Bf0.z, Bf0.w);
            unsigned long long bp2 = pk2(Bf1.x, Bf1.y);
            unsigned long long bp3 = pk2(Bf1.z, Bf1.w);
            float am[8] = {Af0.x, Af0.y, Af0.z, Af0.w, Af1.x, Af1.y, Af1.z, Af1.w};
#pragma unroll
            for (int i = 0; i < 8; i++) {
                unsigned long long ap = pk2(am[i], am[i]);
                ffma2(acc[i][0], ap, bp0);
                ffma2(acc[i][1], ap, bp1);
                ffma2(acc[i][2], ap, bp2);
                ffma2(acc[i][3], ap, bp3);
            }
        }
        if (kt < 63) {
            const int nxt = cur ^ 1;
            const int kc = c0 * 4;
            As[nxt][kc+0][r0] = a0.x; As[nxt][kc+1][r0] = a0.y; As[nxt][kc+2][r0] = a0.z; As[nxt][kc+3][r0] = a0.w;
            As[nxt][kc+0][r1] = a1.x; As[nxt][kc+1][r1] = a1.y; As[nxt][kc+2][r1] = a1.z; As[nxt][kc+3][r1] = a1.w;
            Bs[nxt][kc+0][r0] = b0.x; Bs[nxt][kc+1][r0] = b0.y; Bs[nxt][kc+2][r0] = b0.z; Bs[nxt][kc+3][r0] = b0.w;
            Bs[nxt][kc+0][r1] = b1.x; Bs[nxt][kc+1][r1] = b1.y; Bs[nxt][kc+2][r1] = b1.z; Bs[nxt][kc+3][r1] = b1.w;
        }
        __syncthreads();
    }

    float* out = g_proj + (size_t)seg * SEGC + (size_t)mBase * DD + nBase;
#pragma unroll
    for (int i = 0; i < 8; i++) {
        float4 v0, v1;
        v0.x = lo32(acc[i][0]); v0.y = hi32(acc[i][0]);
        v0.z = lo32(acc[i][1]); v0.w = hi32(acc[i][1]);
        v1.x = lo32(acc[i][2]); v1.y = hi32(acc[i][2]);
        v1.z = lo32(acc[i][3]); v1.w = hi32(acc[i][3]);
        *(float4*)(out + (size_t)(m0 + i) * DD + n0)     = v0;
        *(float4*)(out + (size_t)(m0 + i) * DD + n0 + 4) = v1;
    }
}

// =====================================================================
// Kernel 2: per-head post-process: l2norm(q), l2norm(k),
//           alpha = mean(sigmoid(apre+b_alpha)), beta likewise.
// grid = ROWS*HH blocks of 32 threads; each block = one (t*B+b, h) chunk of 64.
// =====================================================================
__device__ __forceinline__ float sigf(float x) { return 1.0f / (1.0f + expf(-x)); }

__global__ __launch_bounds__(32)
void postproc(const float* __restrict__ b_alpha, const float* __restrict__ b_beta)
{
    const int gb = blockIdx.x;           // tb*16 + h
    const int h = gb & 15;
    const int lane = threadIdx.x;
    const size_t row = (size_t)(gb >> 4) * DD + h * 64 + lane * 2;

    float2 q  = *(float2*)(g_proj + row);
    float2 k  = *(float2*)(g_proj + (size_t)SEGC + row);
    float2 ap = *(float2*)(g_proj + 3ull * SEGC + row);
    float2 bp = *(float2*)(g_proj + 4ull * SEGC + row);
    float2 ba = *(const float2*)(b_alpha + h * 64 + lane * 2);
    float2 bbv = *(const float2*)(b_beta + h * 64 + lane * 2);

    float sq = fmaf(q.x, q.x, q.y * q.y);
    float sk = fmaf(k.x, k.x, k.y * k.y);
    float sa = sigf(ap.x + ba.x) + sigf(ap.y + ba.y);
    float sb = sigf(bp.x + bbv.x) + sigf(bp.y + bbv.y);
#pragma unroll
    for (int m = 16; m; m >>= 1) {
        sq += __shfl_xor_sync(0xffffffffu, sq, m);
        sk += __shfl_xor_sync(0xffffffffu, sk, m);
        sa += __shfl_xor_sync(0xffffffffu, sa, m);
        sb += __shfl_xor_sync(0xffffffffu, sb, m);
    }
    const float qi = 1.0f / fmaxf(sqrtf(sq), 1e-12f);
    const float ki = 1.0f / fmaxf(sqrtf(sk), 1e-12f);
    q.x *= qi; q.y *= qi;
    k.x *= ki; k.y *= ki;
    *(float2*)(g_proj + row) = q;
    *(float2*)(g_proj + (size_t)SEGC + row) = k;
    if (lane == 0) {
        g_alpha[gb] = sa * (1.0f / 64.0f);
        g_beta[gb]  = sb * (1.0f / 64.0f);
    }
}

// =====================================================================
// Kernel 3: sequential gated-delta scan.
// 128 blocks (one per (b,h)); 256 threads = 64 rows x 4 quarters.
// Thread (d, qu) owns S[d][qu*16 .. qu*16+15] in registers.
// 4-slot smem ring with cp.async prefetch depth 3.
// =====================================================================
#define UPD(sv, kv, qv, oacc) { sv = fmaf(coef, kv, a * sv); oacc = fmaf(sv, qv, oacc); }

__global__ __launch_bounds__(256, 1)
void scan(const float* __restrict__ S0, float* __restrict__ out)
{
    const int bh = blockIdx.x;            // b*16 + h
    const int b = bh >> 4, h = bh & 15;
    const int tid = threadIdx.x;
    const int d = tid >> 2, qu = tid & 3;

    // load initial state
    const float4* Sp = (const float4*)(S0 + ((size_t)bh * 64 + d) * 64 + qu * 16);
    float4 s0 = Sp[0], s1 = Sp[1], s2 = Sp[2], s3 = Sp[3];

    __shared__ __align__(16) float4 stg[4][48];   // [slot][0..15]=k, [16..31]=q, [32..47]=v
    __shared__ float2 sab[4];

    const size_t base = (size_t)b * DD + h * 64;
    const float* qb = g_proj + base;
    const float* kb = g_proj + (size_t)SEGC + base;
    const float* vb = g_proj + 2ull * SEGC + base;

    auto issue = [&](int t) {
        const int slot = t & 3;
        if (tid < 48) {
            const int w = tid >> 4;
            const float* src = (w == 0 ? kb : (w == 1 ? qb : vb))
                               + (size_t)t * (BB * DD) + (tid & 15) * 4;
            cpa16(&stg[slot][tid], src);
        } else if (tid == 48) {
            cpa4(&sab[slot].x, g_alpha + t * (BB * HH) + bh);
        } else if (tid == 49) {
            cpa4(&sab[slot].y, g_beta + t * (BB * HH) + bh);
        }
    };

    issue(0); CP_COMMIT();
    issue(1); CP_COMMIT();
    issue(2); CP_COMMIT();

    const size_t ob = (size_t)b * DD + h * 64 + d;

    for (int t = 0; t < TT; t++) {
        CP_WAIT2();
        __syncthreads();
        const int slot = t & 3;
        float4 k0 = stg[slot][qu * 4 + 0];
        float4 k1 = stg[slot][qu * 4 + 1];
        float4 k2 = stg[slot][qu * 4 + 2];
        float4 k3 = stg[slot][qu * 4 + 3];
        float4 q0 = stg[slot][16 + qu * 4 + 0];
        float4 q1 = stg[slot][16 + qu * 4 + 1];
        float4 q2 = stg[slot][16 + qu * 4 + 2];
        float4 q3 = stg[slot][16 + qu * 4 + 3];
        const float a  = sab[slot].x;
        const float be = sab[slot].y;
        const float vv = ((const float*)&stg[slot][32])[d];

        float t0 = fmaf(s0.x, k0.x, fmaf(s0.y, k0.y, fmaf(s0.z, k0.z, s0.w * k0.w)));
        float t1 = fmaf(s1.x, k1.x, fmaf(s1.y, k1.y, fmaf(s1.z, k1.z, s1.w * k1.w)));
        float t2 = fmaf(s2.x, k2.x, fmaf(s2.y, k2.y, fmaf(s2.z, k2.z, s2.w * k2.w)));
        float t3 = fmaf(s3.x, k3.x, fmaf(s3.y, k3.y, fmaf(s3.z, k3.z, s3.w * k3.w)));
        float sk = (t0 + t1) + (t2 + t3);
        sk += __shfl_xor_sync(0xffffffffu, sk, 1);
        sk += __shfl_xor_sync(0xffffffffu, sk, 2);

        const float coef = be * fmaf(-a, sk, vv);

        float o0 = 0.f, o1 = 0.f, o2 = 0.f, o3 = 0.f;
        UPD(s0.x, k0.x, q0.x, o0); UPD(s0.y, k0.y, q0.y, o1);
        UPD(s0.z, k0.z, q0.z, o2); UPD(s0.w, k0.w, q0.w, o3);
        UPD(s1.x, k1.x, q1.x, o0); UPD(s1.y, k1.y, q1.y, o1);
        UPD(s1.z, k1.z, q1.z, o2); UPD(s1.w, k1.w, q1.w, o3);
        UPD(s2.x, k2.x, q2.x, o0); UPD(s2.y, k2.y, q2.y, o1);
        UPD(s2.z, k2.z, q2.z, o2); UPD(s2.w, k2.w, q2.w, o3);
        UPD(s3.x, k3.x, q3.x, o0); UPD(s3.y, k3.y, q3.y, o1);
        UPD(s3.z, k3.z, q3.z, o2); UPD(s3.w, k3.w, q3.w, o3);

        float oo = (o0 + o1) + (o2 + o3);
        oo += __shfl_xor_sync(0xffffffffu, oo, 1);
        oo += __shfl_xor_sync(0xffffffffu, oo, 2);
        if (qu == 0) out[(size_t)t * (BB * DD) + ob] = oo;

        if (t + 3 < TT) issue(t + 3);
        CP_COMMIT();
    }

    // final state -> d_out tail region (B,H,DH,DH)
    float4* So = (float4*)(out + (size_t)(TT * BB * DD) + ((size_t)bh * 64 + d) * 64 + qu * 16);
    So[0] = s0; So[1] = s1; So[2] = s2; So[3] = s3;
}

// =====================================================================
extern "C" void kernel_launch(void* const* d_in, const int* in_sizes, int n_in,
                              void* d_out, int out_size)
{
    const float* x  = (const float*)d_in[0];
    const float* S0 = (const float*)d_in[1];
    const float* Wq = (const float*)d_in[2];
    const float* Wk = (const float*)d_in[3];
    const float* Wv = (const float*)d_in[4];
    const float* Wa = (const float*)d_in[5];
    const float* ba = (const float*)d_in[6];
    const float* Wb = (const float*)d_in[7];
    const float* bb = (const float*)d_in[8];
    float* out = (float*)d_out;

    dim3 gg(64, 40);
    gemm5<<<gg, 256>>>(x, Wq, Wk, Wv, Wa, Wb);
    postproc<<<ROWS * HH, 32>>>(ba, bb);
    scan<<<BB * HH, 256>>>(S0, out);
}

// round 5
// speedup vs baseline: 1.8152x; 1.8152x over previous
#include <cuda_runtime.h>
#include <cuda_bf16.h>
#include <cstdint>

// ---------------- problem dims ----------------
#define TT 1024
#define BB 8
#define DD 1024
#define HH 16
#define ROWS 8192
#define SEGC 8388608u
#define KC 3072                 // concatenated split-bf16 K (hi|hi|lo vs hi|lo|hi)

// ---------------- device scratch ----------------
__device__ float g_proj[5ull * SEGC];     // q,k,v,apre,bpre (fp32)
__device__ float g_alpha[ROWS * HH];
__device__ float g_beta[ROWS * HH];
__device__ __align__(16) __nv_bfloat16 g_xcat[(size_t)ROWS * KC];   // 48 MB
__device__ __align__(16) __nv_bfloat16 g_wcat[(size_t)5120 * KC];   // 30 MB

// ---------------- helpers ----------------
__device__ __forceinline__ uint32_t smem_u32(const void* p) {
    uint32_t a;
    asm("{ .reg .u64 t; cvta.to.shared.u64 t, %1; cvt.u32.u64 %0, t; }" : "=r"(a) : "l"(p));
    return a;
}
__device__ __forceinline__ void cpa16(uint32_t dst, const void* src) {
    asm volatile("cp.async.cg.shared.global [%0], [%1], 16;" :: "r"(dst), "l"(src));
}
#define CP_COMMIT() asm volatile("cp.async.commit_group;")
#define CP_WAIT2()  asm volatile("cp.async.wait_group 2;")

__device__ __forceinline__ void ldm4(uint32_t* r, uint32_t a) {
    asm volatile("ldmatrix.sync.aligned.m8n8.x4.shared.b16 {%0,%1,%2,%3}, [%4];"
        : "=r"(r[0]), "=r"(r[1]), "=r"(r[2]), "=r"(r[3]) : "r"(a));
}
__device__ __forceinline__ void mma16816(float* d, const uint32_t* a, uint32_t b0, uint32_t b1) {
    asm volatile(
        "mma.sync.aligned.m16n8k16.row.col.f32.bf16.bf16.f32 "
        "{%0,%1,%2,%3},{%4,%5,%6,%7},{%8,%9},{%0,%1,%2,%3};"
        : "+f"(d[0]), "+f"(d[1]), "+f"(d[2]), "+f"(d[3])
        : "r"(a[0]), "r"(a[1]), "r"(a[2]), "r"(a[3]), "r"(b0), "r"(b1));
}

// split one float into bf16 hi + bf16 lo
__device__ __forceinline__ void split2(float f0, float f1, uint32_t& hw, uint32_t& lw) {
    __nv_bfloat16 h0 = __float2bfloat16(f0);
    __nv_bfloat16 h1 = __float2bfloat16(f1);
    __nv_bfloat16 l0 = __float2bfloat16(f0 - __bfloat162float(h0));
    __nv_bfloat16 l1 = __float2bfloat16(f1 - __bfloat162float(h1));
    hw = (uint32_t)__bfloat16_as_ushort(h0) | ((uint32_t)__bfloat16_as_ushort(h1) << 16);
    lw = (uint32_t)__bfloat16_as_ushort(l0) | ((uint32_t)__bfloat16_as_ushort(l1) << 16);
}

// =====================================================================
// pack_x: X (8192,1024) fp32 -> Xcat (8192,3072) bf16 = [hi | hi | lo]
// =====================================================================
__global__ __launch_bounds__(256)
void pack_x(const float* __restrict__ x)
{
    unsigned idx = blockIdx.x * 256 + threadIdx.x;   // 1,048,576
    unsigned e = idx * 8;
    unsigned row = e >> 10, col = e & 1023;
    float4 f0 = *(const float4*)(x + e);
    float4 f1 = *(const float4*)(x + e + 4);
    uint4 hi, lo;
    split2(f0.x, f0.y, hi.x, lo.x);
    split2(f0.z, f0.w, hi.y, lo.y);
    split2(f1.x, f1.y, hi.z, lo.z);
    split2(f1.z, f1.w, hi.w, lo.w);
    __nv_bfloat16* base = g_xcat + (size_t)row * KC;
    *(uint4*)(base + col)        = hi;
    *(uint4*)(base + col + 1024) = hi;
    *(uint4*)(base + col + 2048) = lo;
}

// =====================================================================
// pack_w: 5x W (1024,1024) fp32 -> Wcat (5120,3072) bf16 = [hi | lo | hi]
// =====================================================================
__global__ __launch_bounds__(256)
void pack_w(const float* __restrict__ W0, const float* __restrict__ W1,
            const float* __restrict__ W2, const float* __restrict__ W3,
            const float* __restrict__ W4)
{
    unsigned idx = blockIdx.x * 256 + threadIdx.x;   // 655,360
    unsigned e = idx * 8;
    unsigned seg = e >> 20;
    unsigned n = (e >> 10) & 1023, k = e & 1023;
    const float* W = (seg == 0) ? W0 : (seg == 1) ? W1 : (seg == 2) ? W2
                     : (seg == 3) ? W3 : W4;
    const float* src = W + (size_t)n * 1024 + k;
    float4 f0 = *(const float4*)(src);
    float4 f1 = *(const float4*)(src + 4);
    uint4 hi, lo;
    split2(f0.x, f0.y, hi.x, lo.x);
    split2(f0.z, f0.w, hi.y, lo.y);
    split2(f1.x, f1.y, hi.z, lo.z);
    split2(f1.z, f1.w, hi.w, lo.w);
    __nv_bfloat16* base = g_wcat + (size_t)(seg * 1024 + n) * KC;
    *(uint4*)(base + k)        = hi;
    *(uint4*)(base + k + 1024) = lo;
    *(uint4*)(base + k + 2048) = hi;
}

// =====================================================================
// gemm_mma: C(8192,5120) = Xcat @ Wcat^T, bf16 mma.sync, fp32 accum.
// BM=BN=128, BK=32, 4-stage cp.async pipeline (3 in flight), 8 warps,
// warp tile 64x32. Smem rows padded to 80B -> conflict-free ldmatrix.
// grid = 2560 (mt 64 x nt 40).
// =====================================================================
#define STG 20480               // bytes per stage: A 128*80 + B 128*80

__global__ __launch_bounds__(256, 2)
void gemm_mma()
{
    extern __shared__ __align__(16) unsigned char sm[];
    const uint32_t smb = smem_u32(sm);

    const int bid = blockIdx.x;
    const int mt = bid / 40, nt = bid % 40;
    const int tid = threadIdx.x;
    const int lane = tid & 31, wid = tid >> 5;
    const int wm = wid & 1, wn = wid >> 1;

    // global->smem load mapping: 256 threads x 16B, 2 row-passes per operand
    const int lrow = tid >> 2, lch = tid & 3;
    const __nv_bfloat16* Ag = g_xcat + (size_t)(mt * 128 + lrow) * KC + lch * 8;
    const __nv_bfloat16* Bg = g_wcat + (size_t)(nt * 128 + lrow) * KC + lch * 8;
    const uint32_t sA = smb + lrow * 80 + lch * 16;
    const uint32_t sB = smb + 10240 + lrow * 80 + lch * 16;

    auto load = [&](int it, int stage) {
        const uint32_t off = stage * STG;
        const __nv_bfloat16* ag = Ag + it * 32;
        const __nv_bfloat16* bg = Bg + it * 32;
        cpa16(sA + off,           ag);
        cpa16(sA + off + 64 * 80, ag + (size_t)64 * KC);
        cpa16(sB + off,           bg);
        cpa16(sB + off + 64 * 80, bg + (size_t)64 * KC);
    };

    // ldmatrix base addresses (stage 0, kstep 0)
    uint32_t aAddr[4], bAddr[2];
#pragma unroll
    for (int f = 0; f < 4; f++)
        aAddr[f] = smb + (wm * 64 + f * 16 + (lane & 15)) * 80 + (lane >> 4) * 16;
#pragma unroll
    for (int x = 0; x < 2; x++)
        bAddr[x] = smb + 10240 + (wn * 32 + x * 16 + (lane & 15)) * 80 + (lane >> 4) * 16;

    float acc[4][4][4];
#pragma unroll
    for (int f = 0; f < 4; f++)
#pragma unroll
        for (int g = 0; g < 4; g++)
#pragma unroll
            for (int i = 0; i < 4; i++) acc[f][g][i] = 0.f;

    // prologue: fill 3 of 4 stages -> 3 groups in flight
    load(0, 0); CP_COMMIT();
    load(1, 1); CP_COMMIT();
    load(2, 2); CP_COMMIT();

    const int NIT = KC / 32;    // 96
    for (int it = 0; it < NIT; it++) {
        CP_WAIT2();             // 3 pending -> oldest (stage it%4) complete
        __syncthreads();
        if (it + 3 < NIT) load(it + 3, (it + 3) & 3);
        CP_COMMIT();            // exactly one commit per iter keeps pending==3

        const uint32_t st = (it & 3) * STG;
#pragma unroll
        for (int ks = 0; ks < 2; ks++) {
            uint32_t af[4][4], bf[2][4];
#pragma unroll
            for (int f = 0; f < 4; f++) ldm4(af[f], aAddr[f] + st + ks * 32);
#pragma unroll
            for (int x = 0; x < 2; x++) ldm4(bf[x], bAddr[x] + st + ks * 32);
#pragma unroll
            for (int f = 0; f < 4; f++) {
#pragma unroll
                for (int g = 0; g < 4; g++) {
                    const uint32_t b0 = bf[g >> 1][g & 1];
                    const uint32_t b1 = bf[g >> 1][(g & 1) + 2];
                    mma16816(acc[f][g], af[f], b0, b1);
                }
            }
        }
    }

    // epilogue: direct fp32 stores to g_proj (seg, 8192, 1024)
    const int seg = nt >> 3;
    float* op = g_proj + (size_t)seg * SEGC;
    const int rbase = mt * 128 + wm * 64 + (lane >> 2);
    const int cbase = (nt & 7) * 128 + wn * 32 + (lane & 3) * 2;
#pragma unroll
    for (int f = 0; f < 4; f++) {
#pragma unroll
        for (int g = 0; g < 4; g++) {
            const int r = rbase + f * 16;
            const int c = cbase + g * 8;
            float2 v0 = make_float2(acc[f][g][0], acc[f][g][1]);
            float2 v1 = make_float2(acc[f][g][2], acc[f][g][3]);
            *(float2*)(op + (size_t)r * 1024 + c)       = v0;
            *(float2*)(op + (size_t)(r + 8) * 1024 + c) = v1;
        }
    }
}

// =====================================================================
// postproc: l2norm(q,k), alpha/beta = mean(sigmoid(pre + bias))
// =====================================================================
__device__ __forceinline__ float sigf(float x) { return 1.0f / (1.0f + expf(-x)); }

__global__ __launch_bounds__(32)
void postproc(const float* __restrict__ b_alpha, const float* __restrict__ b_beta)
{
    const int gb = blockIdx.x;
    const int h = gb & 15;
    const int lane = threadIdx.x;
    const size_t row = (size_t)(gb >> 4) * DD + h * 64 + lane * 2;

    float2 q  = *(float2*)(g_proj + row);
    float2 k  = *(float2*)(g_proj + (size_t)SEGC + row);
    float2 ap = *(float2*)(g_proj + 3ull * SEGC + row);
    float2 bp = *(float2*)(g_proj + 4ull * SEGC + row);
    float2 ba = *(const float2*)(b_alpha + h * 64 + lane * 2);
    float2 bbv = *(const float2*)(b_beta + h * 64 + lane * 2);

    float sq = fmaf(q.x, q.x, q.y * q.y);
    float sk = fmaf(k.x, k.x, k.y * k.y);
    float sa = sigf(ap.x + ba.x) + sigf(ap.y + ba.y);
    float sb = sigf(bp.x + bbv.x) + sigf(bp.y + bbv.y);
#pragma unroll
    for (int m = 16; m; m >>= 1) {
        sq += __shfl_xor_sync(0xffffffffu, sq, m);
        sk += __shfl_xor_sync(0xffffffffu, sk, m);
        sa += __shfl_xor_sync(0xffffffffu, sa, m);
        sb += __shfl_xor_sync(0xffffffffu, sb, m);
    }
    const float qi = 1.0f / fmaxf(sqrtf(sq), 1e-12f);
    const float ki = 1.0f / fmaxf(sqrtf(sk), 1e-12f);
    q.x *= qi; q.y *= qi;
    k.x *= ki; k.y *= ki;
    *(float2*)(g_proj + row) = q;
    *(float2*)(g_proj + (size_t)SEGC + row) = k;
    if (lane == 0) {
        g_alpha[gb] = sa * (1.0f / 64.0f);
        g_beta[gb]  = sb * (1.0f / 64.0f);
    }
}

// =====================================================================
// scan: register-resident 4-slot prefetch, no smem, no block syncs.
// 128 blocks (one per (b,h)); 256 threads = 64 rows x 4 col-quarters.
// =====================================================================
#define UPD(sv, kv, qv, oacc) { sv = fmaf(coef, kv, a * sv); oacc = fmaf(sv, qv, oacc); }

#define LOADS(S, t) { \
    const float4* kp = (const float4*)(kb + (size_t)(t) * 8192) + (qu * 4); \
    kr##S##_0 = kp[0]; kr##S##_1 = kp[1]; kr##S##_2 = kp[2]; kr##S##_3 = kp[3]; \
    const float4* qp = (const float4*)(qb + (size_t)(t) * 8192) + (qu * 4); \
    qr##S##_0 = qp[0]; qr##S##_1 = qp[1]; qr##S##_2 = qp[2]; qr##S##_3 = qp[3]; \
    vr##S = vb[(size_t)(t) * 8192 + d]; \
    ar##S = g_alpha[(t) * 128 + bh]; \
    br##S = g_beta[(t) * 128 + bh]; }

#define STEP(S, tt) { \
    const float a = ar##S, be = br##S, vv = vr##S; \
    float t0 = fmaf(s0.x, kr##S##_0.x, fmaf(s0.y, kr##S##_0.y, fmaf(s0.z, kr##S##_0.z, s0.w * kr##S##_0.w))); \
    float t1 = fmaf(s1.x, kr##S##_1.x, fmaf(s1.y, kr##S##_1.y, fmaf(s1.z, kr##S##_1.z, s1.w * kr##S##_1.w))); \
    float t2 = fmaf(s2.x, kr##S##_2.x, fmaf(s2.y, kr##S##_2.y, fmaf(s2.z, kr##S##_2.z, s2.w * kr##S##_2.w))); \
    float t3 = fmaf(s3.x, kr##S##_3.x, fmaf(s3.y, kr##S##_3.y, fmaf(s3.z, kr##S##_3.z, s3.w * kr##S##_3.w))); \
    float sk = (t0 + t1) + (t2 + t3); \
    sk += __shfl_xor_sync(0xffffffffu, sk, 1); \
    sk += __shfl_xor_sync(0xffffffffu, sk, 2); \
    const float coef = be * fmaf(-a, sk, vv); \
    float o0 = 0.f, o1 = 0.f, o2 = 0.f, o3 = 0.f; \
    UPD(s0.x, kr##S##_0.x, qr##S##_0.x, o0); UPD(s0.y, kr##S##_0.y, qr##S##_0.y, o1); \
    UPD(s0.z, kr##S##_0.z, qr##S##_0.z, o2); UPD(s0.w, kr##S##_0.w, qr##S##_0.w, o3); \
    UPD(s1.x, kr##S##_1.x, qr##S##_1.x, o0); UPD(s1.y, kr##S##_1.y, qr##S##_1.y, o1); \
    UPD(s1.z, kr##S##_1.z, qr##S##_1.z, o2); UPD(s1.w, kr##S##_1.w, qr##S##_1.w, o3); \
    UPD(s2.x, kr##S##_2.x, qr##S##_2.x, o0); UPD(s2.y, kr##S##_2.y, qr##S##_2.y, o1); \
    UPD(s2.z, kr##S##_2.z, qr##S##_2.z, o2); UPD(s2.w, kr##S##_2.w, qr##S##_2.w, o3); \
    UPD(s3.x, kr##S##_3.x, qr##S##_3.x, o0); UPD(s3.y, kr##S##_3.y, qr##S##_3.y, o1); \
    UPD(s3.z, kr##S##_3.z, qr##S##_3.z, o2); UPD(s3.w, kr##S##_3.w, qr##S##_3.w, o3); \
    float oo = (o0 + o1) + (o2 + o3); \
    oo += __shfl_xor_sync(0xffffffffu, oo, 1); \
    oo += __shfl_xor_sync(0xffffffffu, oo, 2); \
    if (qu == 0) out[(size_t)(tt) * 8192 + ob] = oo; \
    if ((tt) + 4 < TT) LOADS(S, (tt) + 4); }

__global__ __launch_bounds__(256, 1)
void scan(const float* __restrict__ S0, float* __restrict__ out)
{
    const int bh = blockIdx.x;
    const int b = bh >> 4, h = bh & 15;
    const int tid = threadIdx.x;
    const int d = tid >> 2, qu = tid & 3;

    const float4* Sp = (const float4*)(S0 + ((size_t)bh * 64 + d) * 64 + qu * 16);
    float4 s0 = Sp[0], s1 = Sp[1], s2 = Sp[2], s3 = Sp[3];

    const size_t base = (size_t)b * DD + h * 64;
    const float* qb = g_proj + base;
    const float* kb = g_proj + (size_t)SEGC + base;
    const float* vb = g_proj + 2ull * SEGC + base;
    const size_t ob = (size_t)b * DD + h * 64 + d;

    float4 kr0_0, kr0_1, kr0_2, kr0_3, qr0_0, qr0_1, qr0_2, qr0_3;
    float4 kr1_0, kr1_1, kr1_2, kr1_3, qr1_0, qr1_1, qr1_2, qr1_3;
    float4 kr2_0, kr2_1, kr2_2, kr2_3, qr2_0, qr2_1, qr2_2, qr2_3;
    float4 kr3_0, kr3_1, kr3_2, kr3_3, qr3_0, qr3_1, qr3_2, qr3_3;
    float vr0, ar0, br0, vr1, ar1, br1, vr2, ar2, br2, vr3, ar3, br3;

    LOADS(0, 0); LOADS(1, 1); LOADS(2, 2); LOADS(3, 3);

    for (int t = 0; t < TT; t += 4) {
        STEP(0, t);
        STEP(1, t + 1);
        STEP(2, t + 2);
        STEP(3, t + 3);
    }

    float4* So = (float4*)(out + (size_t)(TT * BB * DD) + ((size_t)bh * 64 + d) * 64 + qu * 16);
    So[0] = s0; So[1] = s1; So[2] = s2; So[3] = s3;
}

// =====================================================================
extern "C" void kernel_launch(void* const* d_in, const int* in_sizes, int n_in,
                              void* d_out, int out_size)
{
    const float* x  = (const float*)d_in[0];
    const float* S0 = (const float*)d_in[1];
    const float* Wq = (const float*)d_in[2];
    const float* Wk = (const float*)d_in[3];
    const float* Wv = (const float*)d_in[4];
    const float* Wa = (const float*)d_in[5];
    const float* ba = (const float*)d_in[6];
    const float* Wb = (const float*)d_in[7];
    const float* bb = (const float*)d_in[8];
    float* out = (float*)d_out;

    cudaFuncSetAttribute(gemm_mma, cudaFuncAttributeMaxDynamicSharedMemorySize, 4 * STG);

    pack_x<<<4096, 256>>>(x);
    pack_w<<<2560, 256>>>(Wq, Wk, Wv, Wa, Wb);
    gemm_mma<<<2560, 256, 4 * STG>>>();
    postproc<<<ROWS * HH, 32>>>(ba, bb);
    scan<<<BB * HH, 256>>>(S0, out);
}